// round 1
// baseline (speedup 1.0000x reference)
#include <cuda_runtime.h>
#include <math.h>

// Problem constants
#define Nn    1024
#define Bb    4
#define Tt    8
#define BT    32          // Bb*Tt
#define INDIM 64
#define Hh    4
#define HIDd  64
#define FD    256         // Hh*HIDd
#define M_TOT 32768       // Nn*BT
#define Kconv 1018
#define EPS_  1e-5f

// ---------------- scratch (device globals; no runtime allocation) -----------
__device__ float g_h   [M_TOT * INDIM]; // transposed input (m, i)
__device__ float g_feat[M_TOT * FD];    // current layer's feat = h @ W^T
__device__ float g_h1  [M_TOT * FD];    // layer-0 output
__device__ float g_h2  [M_TOT * FD];    // layer-1 output
__device__ float g_el  [M_TOT * Hh];
__device__ float g_er  [M_TOT * Hh];
__device__ float g_sm8 [M_TOT * 8];     // [0..3]=feat2, [4..7]=res2
__device__ float g_o   [M_TOT * Hh];    // layer-2 output

// ---------------- 1) transpose: inputs(B,IN,T,N) -> g_h[(n*BT+bt)*64 + i] ---
__global__ __launch_bounds__(256) void transpose_kernel(const float* __restrict__ inp) {
    __shared__ float tile[64][129];
    int bt = blockIdx.x;               // 0..31
    int b  = bt >> 3, t = bt & 7;
    int n0 = blockIdx.y * 128;
    int tid = threadIdx.x;
    for (int li = tid; li < 64 * 128; li += 256) {
        int i = li >> 7, nl = li & 127;
        tile[i][nl] = inp[((b * 64 + i) * 8 + t) * 1024 + n0 + nl];
    }
    __syncthreads();
    for (int lo = tid; lo < 64 * 128; lo += 256) {
        int nl = lo >> 6, i = lo & 63;
        g_h[(size_t)((n0 + nl) * BT + bt) * 64 + i] = tile[i][nl];
    }
}

// ---------------- 2) SGEMM: C[m,j] = sum_k A[m,k]*W[j,k] -------------------
// layer==0: A=g_h  (K=64),  C=g_feat ;  layer==1: A=g_h1 (K=256), C=g_feat
__global__ __launch_bounds__(256) void sgemm_kernel(const float* __restrict__ W, int layer) {
    const float* __restrict__ A = layer ? g_h1 : g_h;
    float* __restrict__ C = g_feat;
    const int K = layer ? 256 : 64;
    __shared__ __align__(16) float As[16][132];
    __shared__ __align__(16) float Ws[16][68];
    int tid = threadIdx.x;
    int m0 = blockIdx.y * 128;
    int j0 = blockIdx.x * 64;
    int tx = tid & 15, ty = tid >> 4;
    float acc[8][4];
#pragma unroll
    for (int i = 0; i < 8; i++)
#pragma unroll
        for (int q = 0; q < 4; q++) acc[i][q] = 0.f;

    for (int k0 = 0; k0 < K; k0 += 16) {
        int idx = tid;
#pragma unroll
        for (int r = 0; r < 2; r++, idx += 256) {
            int row = idx >> 2, c4 = idx & 3;
            const float4 v = *reinterpret_cast<const float4*>(A + (size_t)(m0 + row) * K + k0 + c4 * 4);
            As[c4 * 4 + 0][row] = v.x; As[c4 * 4 + 1][row] = v.y;
            As[c4 * 4 + 2][row] = v.z; As[c4 * 4 + 3][row] = v.w;
        }
        {
            int jrow = tid >> 2, c4 = tid & 3;
            const float4 v = *reinterpret_cast<const float4*>(W + (size_t)(j0 + jrow) * K + k0 + c4 * 4);
            Ws[c4 * 4 + 0][jrow] = v.x; Ws[c4 * 4 + 1][jrow] = v.y;
            Ws[c4 * 4 + 2][jrow] = v.z; Ws[c4 * 4 + 3][jrow] = v.w;
        }
        __syncthreads();
#pragma unroll
        for (int kk = 0; kk < 16; kk++) {
            float4 a0 = *reinterpret_cast<const float4*>(&As[kk][ty * 8]);
            float4 a1 = *reinterpret_cast<const float4*>(&As[kk][ty * 8 + 4]);
            float4 wv = *reinterpret_cast<const float4*>(&Ws[kk][tx * 4]);
            float a[8] = {a0.x, a0.y, a0.z, a0.w, a1.x, a1.y, a1.z, a1.w};
            float wq[4] = {wv.x, wv.y, wv.z, wv.w};
#pragma unroll
            for (int i = 0; i < 8; i++)
#pragma unroll
                for (int q = 0; q < 4; q++) acc[i][q] += a[i] * wq[q];
        }
        __syncthreads();
    }
#pragma unroll
    for (int i = 0; i < 8; i++) {
        float4 v = make_float4(acc[i][0], acc[i][1], acc[i][2], acc[i][3]);
        *reinterpret_cast<float4*>(C + (size_t)(m0 + ty * 8 + i) * FD + j0 + tx * 4) = v;
    }
}

// ---------------- 3) el/er: warp per m, dot(feat[m,h,:], al/ar[h,:]) -------
__global__ __launch_bounds__(256) void eler_kernel(const float* __restrict__ al,
                                                   const float* __restrict__ ar) {
    __shared__ float alsm[256], arsm[256];
    int tid = threadIdx.x;
    alsm[tid] = al[tid];
    arsm[tid] = ar[tid];
    __syncthreads();
    int w = tid >> 5, lane = tid & 31;
    int m = blockIdx.x * 8 + w;
    float fv[8];
#pragma unroll
    for (int q = 0; q < 8; q++) fv[q] = g_feat[(size_t)m * FD + q * 32 + lane];
#pragma unroll
    for (int h = 0; h < 4; h++) {
        float sl = fv[2 * h] * alsm[2 * h * 32 + lane] + fv[2 * h + 1] * alsm[(2 * h + 1) * 32 + lane];
        float sr = fv[2 * h] * arsm[2 * h * 32 + lane] + fv[2 * h + 1] * arsm[(2 * h + 1) * 32 + lane];
#pragma unroll
        for (int o = 16; o >= 1; o >>= 1) {
            sl += __shfl_xor_sync(0xffffffffu, sl, o);
            sr += __shfl_xor_sync(0xffffffffu, sr, o);
        }
        if (lane == 0) { g_el[m * 4 + h] = sl; g_er[m * 4 + h] = sr; }
    }
}

// ---------------- 4) GAT aggregate (layers 0 & 1) --------------------------
// layer==0: out=g_h1, no residual; layer==1: out=g_h2, res=g_h1. elu both.
__global__ __launch_bounds__(256) void aggregate_kernel(const int* __restrict__ src, int layer) {
    __shared__ int   ssm[8];
    __shared__ float a_sm[4][8];
    int n = blockIdx.x, bt = blockIdx.y;
    int m = n * BT + bt;
    int tid = threadIdx.x;
    if (tid < 8) ssm[tid] = src[n * 8 + tid];
    __syncthreads();
    if (tid < 4) {
        int h = tid;
        float er_v = g_er[m * 4 + h];
        float e[8];
        float mx = -1e30f;
#pragma unroll
        for (int j = 0; j < 8; j++) {
            float v = g_el[(ssm[j] * BT + bt) * 4 + h] + er_v;
            v = v > 0.f ? v : 0.2f * v;          // leaky_relu(0.2)
            e[j] = v;
            mx = fmaxf(mx, v);
        }
        float den = 0.f;
#pragma unroll
        for (int j = 0; j < 8; j++) { e[j] = expf(e[j] - mx); den += e[j]; }
        float inv = 1.f / den;
#pragma unroll
        for (int j = 0; j < 8; j++) a_sm[h][j] = e[j] * inv;
    }
    __syncthreads();
    int d = tid, h = d >> 6;
    float acc = 0.f;
#pragma unroll
    for (int j = 0; j < 8; j++)
        acc += a_sm[h][j] * g_feat[(size_t)(ssm[j] * BT + bt) * FD + d];
    if (layer == 1) acc += g_h1[(size_t)m * FD + d];          // residual
    acc = acc > 0.f ? acc : expm1f(acc);                      // elu
    if (layer == 1) g_h2[(size_t)m * FD + d] = acc;
    else            g_h1[(size_t)m * FD + d] = acc;
}

// ---------------- 5) feat2 & res2 : 8 dots of 256 per m ---------------------
__global__ __launch_bounds__(256) void smallgemm8_kernel(const float* __restrict__ W2,
                                                         const float* __restrict__ Wres2) {
    __shared__ float wsm[2048];
    int tid = threadIdx.x;
    for (int i = tid; i < 2048; i += 256)
        wsm[i] = (i < 1024) ? W2[i] : Wres2[i - 1024];
    __syncthreads();
    int w = tid >> 5, lane = tid & 31;
    int m = blockIdx.x * 8 + w;
    float hv[8];
#pragma unroll
    for (int q = 0; q < 8; q++) hv[q] = g_h2[(size_t)m * FD + q * 32 + lane];
#pragma unroll
    for (int c = 0; c < 8; c++) {
        float s = 0.f;
#pragma unroll
        for (int q = 0; q < 8; q++) s += hv[q] * wsm[c * 256 + q * 32 + lane];
#pragma unroll
        for (int o = 16; o >= 1; o >>= 1) s += __shfl_xor_sync(0xffffffffu, s, o);
        if (lane == 0) g_sm8[m * 8 + c] = s;
    }
}

// ---------------- 6) GAT layer 2 (d=1), warp per m ---------------------------
__global__ __launch_bounds__(256) void gat2_kernel(const int* __restrict__ src,
                                                   const float* __restrict__ al2,
                                                   const float* __restrict__ ar2) {
    int tid = threadIdx.x;
    int w = tid >> 5, lane = tid & 31;
    int m = blockIdx.x * 8 + w;
    int n = m >> 5, bt = m & 31;
    int h = lane >> 3, j = lane & 7;
    int s = src[n * 8 + j];
    float fs = g_sm8[(s * BT + bt) * 8 + h];
    float e = fs * al2[h] + g_sm8[m * 8 + h] * ar2[h];
    e = e > 0.f ? e : 0.2f * e;
    float mx = e;
#pragma unroll
    for (int o = 4; o >= 1; o >>= 1) mx = fmaxf(mx, __shfl_xor_sync(0xffffffffu, mx, o));
    float ex = expf(e - mx);
    float den = ex;
#pragma unroll
    for (int o = 4; o >= 1; o >>= 1) den += __shfl_xor_sync(0xffffffffu, den, o);
    float val = (ex / den) * fs;
#pragma unroll
    for (int o = 4; o >= 1; o >>= 1) val += __shfl_xor_sync(0xffffffffu, val, o);
    if (j == 0) g_o[m * 4 + h] = val + g_sm8[m * 8 + 4 + h];
}

// ---------------- 7) head: tc1 + LN1 + tc2 + LN2 + conv(K=1018) ------------
__global__ __launch_bounds__(1024) void head_kernel(
    const float* __restrict__ tc1_w, const float* __restrict__ tc1_b,
    const float* __restrict__ ln1_g, const float* __restrict__ ln1_b,
    const float* __restrict__ tc2_w, const float* __restrict__ tc2_b,
    const float* __restrict__ ln2_g, const float* __restrict__ ln2_b,
    const float* __restrict__ fc_w,  const float* __restrict__ fc_b,
    float* __restrict__ out) {
    __shared__ float xb[1024];
    __shared__ float red[2048];
    int b = blockIdx.x;
    int n = threadIdx.x;

    float ov[8][4];
#pragma unroll
    for (int t = 0; t < 8; t++)
#pragma unroll
        for (int h = 0; h < 4; h++)
            ov[t][h] = g_o[(size_t)(n * BT + b * 8 + t) * 4 + h];

    float zr[4];
    float s = 0.f, sq = 0.f;
#pragma unroll
    for (int hh = 0; hh < 4; hh++) {
        float acc = tc1_b[hh];
#pragma unroll
        for (int h = 0; h < 4; h++)
#pragma unroll
            for (int t = 0; t < 8; t++)
                acc += tc1_w[(hh * 4 + h) * 8 + t] * ov[t][h];
        zr[hh] = acc;
        s += acc;
        sq += acc * acc;
    }
    red[n] = s; red[1024 + n] = sq;
    __syncthreads();
    for (int st = 512; st >= 1; st >>= 1) {
        if (n < st) { red[n] += red[n + st]; red[1024 + n] += red[1024 + n + st]; }
        __syncthreads();
    }
    float mu  = red[0] * (1.f / 4096.f);
    float var = red[1024] * (1.f / 4096.f) - mu * mu;
    float rstd = rsqrtf(var + EPS_);
    __syncthreads();   // red about to be reused

    float x2 = tc2_b[0];
#pragma unroll
    for (int hh = 0; hh < 4; hh++) {
        float zn = (zr[hh] - mu) * rstd * ln1_g[n * 4 + hh] + ln1_b[n * 4 + hh];
        x2 += tc2_w[hh] * zn;
    }
    red[n] = x2; red[1024 + n] = x2 * x2;
    __syncthreads();
    for (int st = 512; st >= 1; st >>= 1) {
        if (n < st) { red[n] += red[n + st]; red[1024 + n] += red[1024 + n + st]; }
        __syncthreads();
    }
    float mu2  = red[0] * (1.f / 1024.f);
    float var2 = red[1024] * (1.f / 1024.f) - mu2 * mu2;
    float rstd2 = rsqrtf(var2 + EPS_);
    xb[n] = (x2 - mu2) * rstd2 * ln2_g[n] + ln2_b[n];
    __syncthreads();

    int w = n >> 5, lane = n & 31;
    if (w < 7) {
        float acc = 0.f;
        for (int k = lane; k < Kconv; k += 32)
            acc += xb[w + k] * fc_w[k];
#pragma unroll
        for (int o = 16; o >= 1; o >>= 1) acc += __shfl_xor_sync(0xffffffffu, acc, o);
        if (lane == 0) out[b * 7 + w] = acc + fc_b[0];
    }
}

// ---------------- launch ----------------------------------------------------
extern "C" void kernel_launch(void* const* d_in, const int* in_sizes, int n_in,
                              void* d_out, int out_size) {
    const float* inputs = (const float*)d_in[0];
    const int*   src    = (const int*)  d_in[1];
    // d_in[2] = dst (structurally repeat(arange(N),8); exploited, not read)
    const float* W0     = (const float*)d_in[3];
    const float* al0    = (const float*)d_in[4];
    const float* ar0    = (const float*)d_in[5];
    const float* W1     = (const float*)d_in[6];
    const float* al1    = (const float*)d_in[7];
    const float* ar1    = (const float*)d_in[8];
    const float* W2     = (const float*)d_in[9];
    const float* al2    = (const float*)d_in[10];
    const float* ar2    = (const float*)d_in[11];
    const float* Wres2  = (const float*)d_in[12];
    const float* tc1_w  = (const float*)d_in[13];
    const float* tc1_b  = (const float*)d_in[14];
    const float* ln1_g  = (const float*)d_in[15];
    const float* ln1_b  = (const float*)d_in[16];
    const float* tc2_w  = (const float*)d_in[17];
    const float* tc2_b  = (const float*)d_in[18];
    const float* ln2_g  = (const float*)d_in[19];
    const float* ln2_b  = (const float*)d_in[20];
    const float* fc_w   = (const float*)d_in[21];
    const float* fc_b   = (const float*)d_in[22];
    float* out = (float*)d_out;

    transpose_kernel<<<dim3(32, 8), 256>>>(inputs);

    // layer 0
    sgemm_kernel<<<dim3(4, 256), 256>>>(W0, 0);
    eler_kernel<<<4096, 256>>>(al0, ar0);
    aggregate_kernel<<<dim3(1024, 32), 256>>>(src, 0);

    // layer 1
    sgemm_kernel<<<dim3(4, 256), 256>>>(W1, 1);
    eler_kernel<<<4096, 256>>>(al1, ar1);
    aggregate_kernel<<<dim3(1024, 32), 256>>>(src, 1);

    // layer 2
    smallgemm8_kernel<<<4096, 256>>>(W2, Wres2);
    gat2_kernel<<<4096, 256>>>(src, al2, ar2);

    // head
    head_kernel<<<4, 1024>>>(tc1_w, tc1_b, ln1_g, ln1_b,
                             tc2_w, tc2_b, ln2_g, ln2_b,
                             fc_w, fc_b, out);
}